// round 5
// baseline (speedup 1.0000x reference)
#include <cuda_runtime.h>
#include <math.h>
#include <stdint.h>

#define BATCH 4096
#define TT    15
#define EMBD  300
#define HID   512
#define G3    1536
#define DD    1024
#define BT    (BATCH*TT)
#define VOCAB 12000
#define BH    (BATCH*HID)

#define SROW      36                 // smem row stride in floats (32 + 4 pad)
#define STAGE_U32 (128*SROW)
#define SMEM_B    (2*2*STAGE_U32*4)  // tgemm/attn_w smem: 73728 B

// fused recurrence kernel smem: A(64 rows) + B(384 rows), 2 stages
#define R_A_U32   (64*SROW)          // 2304
#define R_B_U32   (384*SROW)         // 13824
#define R_STAGE   (R_A_U32 + R_B_U32)
#define R_SMEM    (2*R_STAGE*4)      // 129024 B

// ---------------- scratch -----------------------------------------------------
__device__ float g_git_f[(size_t)VOCAB * G3];   // gi table fwd (incl b_ih)
__device__ float g_git_b[(size_t)VOCAB * G3];
__device__ float g_h_f [2 * BH];                // double-buffered hidden state
__device__ float g_h_b [2 * BH];
__device__ float g_yword[(size_t)BT * DD];
__device__ float g_ypool[BATCH * DD];
__device__ float g_gw  [BATCH * DD];
__device__ float g_wraw[BT];

// ---------------- TF32 helpers -------------------------------------------------
__device__ __forceinline__ uint32_t f2tf(float x) {
    uint32_t r; asm("cvt.rna.tf32.f32 %0, %1;" : "=r"(r) : "f"(x)); return r;
}
__device__ __forceinline__ void mma8(float* c,
    uint32_t a0, uint32_t a1, uint32_t a2, uint32_t a3,
    uint32_t b0, uint32_t b1)
{
    asm volatile(
        "mma.sync.aligned.m16n8k8.row.col.f32.tf32.tf32.f32 "
        "{%0,%1,%2,%3},{%4,%5,%6,%7},{%8,%9},{%0,%1,%2,%3};"
        : "+f"(c[0]), "+f"(c[1]), "+f"(c[2]), "+f"(c[3])
        : "r"(a0), "r"(a1), "r"(a2), "r"(a3), "r"(b0), "r"(b1));
}
__device__ __forceinline__ float sigm(float x) { return 1.f / (1.f + expf(-x)); }

// ================= generic 128x128 TF32 GEMM (unchanged from R4) ===============
__device__ __forceinline__ void stage_load(
    const float* const* aptr, const float* const* wptr,
    int k, int K, float4* ra, float4* rb)
{
    const float4 z4 = make_float4(0.f, 0.f, 0.f, 0.f);
    const bool v = (k < K);
    #pragma unroll
    for (int i = 0; i < 4; i++) {
        ra[i] = v ? *(const float4*)(aptr[i] + k) : z4;
        rb[i] = v ? *(const float4*)(wptr[i] + k) : z4;
    }
}
__device__ __forceinline__ void stage_store(
    uint32_t* dst, int lr, int lc4, const float4* ra, const float4* rb)
{
    uint32_t* db = dst + STAGE_U32;
    #pragma unroll
    for (int i = 0; i < 4; i++) {
        const int base = (lr + i * 32) * SROW + lc4;
        dst[base +  0] = f2tf(ra[i].x);
        dst[base +  8] = f2tf(ra[i].y);
        dst[base + 16] = f2tf(ra[i].z);
        dst[base + 24] = f2tf(ra[i].w);
        db [base +  0] = f2tf(rb[i].x);
        db [base +  8] = f2tf(rb[i].y);
        db [base + 16] = f2tf(rb[i].z);
        db [base + 24] = f2tf(rb[i].w);
    }
}
__device__ __forceinline__ void mm_tile(
    const uint32_t* As, const uint32_t* Bs,
    int wm0, int wn0, int g, int q, float (*c)[8][4])
{
    const uint4* As4 = (const uint4*)As;
    const uint4* Bs4 = (const uint4*)Bs;
    #pragma unroll
    for (int h = 0; h < 2; h++) {
        const int fo = q * 2 + h;
        const uint4 aL0 = As4[(wm0 + g     ) * 9 + fo];
        const uint4 aH0 = As4[(wm0 + g +  8) * 9 + fo];
        const uint4 aL1 = As4[(wm0 + g + 16) * 9 + fo];
        const uint4 aH1 = As4[(wm0 + g + 24) * 9 + fo];
        uint4 bf[8];
        #pragma unroll
        for (int nt = 0; nt < 8; nt++)
            bf[nt] = Bs4[(wn0 + nt * 8 + g) * 9 + fo];
        #pragma unroll
        for (int s = 0; s < 2; s++) {
            const uint32_t A00 = s ? aL0.z : aL0.x;
            const uint32_t A20 = s ? aL0.w : aL0.y;
            const uint32_t A10 = s ? aH0.z : aH0.x;
            const uint32_t A30 = s ? aH0.w : aH0.y;
            const uint32_t A01 = s ? aL1.z : aL1.x;
            const uint32_t A21 = s ? aL1.w : aL1.y;
            const uint32_t A11 = s ? aH1.z : aH1.x;
            const uint32_t A31 = s ? aH1.w : aH1.y;
            #pragma unroll
            for (int nt = 0; nt < 8; nt++) {
                const uint32_t B0 = s ? bf[nt].z : bf[nt].x;
                const uint32_t B1 = s ? bf[nt].w : bf[nt].y;
                mma8(c[0][nt], A00, A10, A20, A30, B0, B1);
                mma8(c[1][nt], A01, A11, A21, A31, B0, B1);
            }
        }
    }
}

__global__ void __launch_bounds__(256) tgemm(
    const float* __restrict__ A,  const float* __restrict__ A2, int lda,
    const float* __restrict__ W,  const float* __restrict__ W2,
    const float* __restrict__ bias, const float* __restrict__ bias2,
    const float* __restrict__ wc,
    float* __restrict__ C, float* __restrict__ C2,
    int M, int N, int K, int epi)
{
    if (blockIdx.z == 1) { A = A2; W = W2; bias = bias2; C = C2; }
    extern __shared__ uint32_t sm[];

    const int tid  = threadIdx.x;
    const int lane = tid & 31, wid = tid >> 5;
    const int g = lane >> 2, q = lane & 3;
    const int wm0 = (wid & 3) * 32;
    const int wn0 = (wid >> 2) * 64;
    const int row0 = blockIdx.x * 128;
    const int col0 = blockIdx.y * 128;
    const int lr  = tid >> 3;
    const int lc4 = tid & 7;

    const float* aptr[4];
    const float* wptr[4];
    #pragma unroll
    for (int i = 0; i < 4; i++) {
        int ar = row0 + lr + i * 32;
        if (ar >= M) ar = M - 1;
        aptr[i] = A + (long)ar * lda;
        wptr[i] = W + (long)(col0 + lr + i * 32) * K;
    }

    float c[2][8][4];
    #pragma unroll
    for (int mt = 0; mt < 2; mt++)
        #pragma unroll
        for (int nt = 0; nt < 8; nt++)
            #pragma unroll
            for (int j = 0; j < 4; j++) c[mt][nt][j] = 0.f;

    float4 ra[4], rb[4];
    const int nk = (K + 31) / 32;

    stage_load(aptr, wptr, lc4 * 4, K, ra, rb);
    stage_store(sm, lr, lc4, ra, rb);
    __syncthreads();

    for (int it = 0; it < nk; it++) {
        const bool more = (it + 1 < nk);
        if (more) stage_load(aptr, wptr, (it + 1) * 32 + lc4 * 4, K, ra, rb);
        const uint32_t* cur = sm + (it & 1) * (2 * STAGE_U32);
        mm_tile(cur, cur + STAGE_U32, wm0, wn0, g, q, c);
        if (more) {
            stage_store(sm + ((it + 1) & 1) * (2 * STAGE_U32), lr, lc4, ra, rb);
            __syncthreads();
        }
    }

    #pragma unroll
    for (int mt = 0; mt < 2; mt++) {
        const int r = row0 + wm0 + mt * 16 + g;
        #pragma unroll
        for (int nt = 0; nt < 8; nt++) {
            const int n = col0 + wn0 + nt * 8 + q * 2;
            const float b0 = bias[n], b1 = bias[n + 1];
            float v00 = c[mt][nt][0] + b0, v01 = c[mt][nt][1] + b1;
            float v10 = c[mt][nt][2] + b0, v11 = c[mt][nt][3] + b1;
            if (epi == 1) {
                const float w0 = wc[n], w1 = wc[n + 1];
                v00 = tanhf(v00) * w0; v01 = tanhf(v01) * w1;
                v10 = tanhf(v10) * w0; v11 = tanhf(v11) * w1;
            }
            if (r < M)
                *(float2*)(C + (long)r * N + n) = make_float2(v00, v01);
            if (r + 8 < M)
                *(float2*)(C + (long)(r + 8) * N + n) = make_float2(v10, v11);
        }
    }
}

// ================= fused GRU recurrence step ===================================
// One CTA: 64 batch rows x 128 hidden cols, all 3 gates simultaneously.
// gh = h_prev @ w_hh^T (3 accumulator sets), then full GRU cell in epilogue:
// h_new = (1-z)*n + z*h_prev, written to h_next (double buffer) + y_word.
__global__ void __launch_bounds__(256) rec_step(
    const int* __restrict__ inds,
    const float* __restrict__ git_f, const float* __restrict__ git_b,
    const float* __restrict__ whh_f, const float* __restrict__ whh_b,
    const float* __restrict__ bhh_f, const float* __restrict__ bhh_b,
    const float* __restrict__ hprev_f, const float* __restrict__ hprev_b,
    float* __restrict__ hnext_f, float* __restrict__ hnext_b,
    float* __restrict__ y_word, int t)
{
    const float* git; const float* W; const float* bhh;
    const float* hprev; float* hnext; int tt, off;
    if (blockIdx.z == 0) {
        git = git_f; W = whh_f; bhh = bhh_f; hprev = hprev_f; hnext = hnext_f;
        tt = t; off = 0;
    } else {
        git = git_b; W = whh_b; bhh = bhh_b; hprev = hprev_b; hnext = hnext_b;
        tt = TT - 1 - t; off = HID;
    }

    extern __shared__ uint32_t sm[];

    const int tid  = threadIdx.x;
    const int lane = tid & 31, wid = tid >> 5;
    const int g = lane >> 2, q = lane & 3;
    const int wm0 = (wid & 1) * 32;       // 2 m-warps (32 rows each)
    const int wn0 = (wid >> 1) * 32;      // 4 n-warps (32 cols each)
    const int row0 = blockIdx.x * 64;     // batch tile
    const int col0 = blockIdx.y * 128;    // hidden-unit tile
    const int lr  = tid >> 3;             // 0..31
    const int lc4 = tid & 7;              // k float4 slot

    // A: h_prev rows row0+lr, row0+lr+32 ; B: 384 rows (3 gates x 128 h)
    const float* aptr[2];
    #pragma unroll
    for (int i = 0; i < 2; i++)
        aptr[i] = hprev + (long)(row0 + lr + i * 32) * HID;
    const float* wptr[12];
    #pragma unroll
    for (int i = 0; i < 12; i++) {
        const int r = lr + i * 32;            // 0..383
        const int gate = r >> 7, wi = r & 127;
        wptr[i] = W + (long)(gate * HID + col0 + wi) * HID;
    }

    float c[3][2][4][4];
    #pragma unroll
    for (int gt = 0; gt < 3; gt++)
        #pragma unroll
        for (int mt = 0; mt < 2; mt++)
            #pragma unroll
            for (int nt = 0; nt < 4; nt++)
                #pragma unroll
                for (int j = 0; j < 4; j++) c[gt][mt][nt][j] = 0.f;

    float4 ra[2], rb[12];
    const int nk = HID / 32;  // 16

    // prefetch k0
    #pragma unroll
    for (int i = 0; i < 2; i++)  ra[i] = *(const float4*)(aptr[i] + lc4 * 4);
    #pragma unroll
    for (int i = 0; i < 12; i++) rb[i] = *(const float4*)(wptr[i] + lc4 * 4);
    // store stage 0
    {
        uint32_t* sa = sm;
        uint32_t* sb = sm + R_A_U32;
        #pragma unroll
        for (int i = 0; i < 2; i++) {
            const int base = (lr + i * 32) * SROW + lc4;
            sa[base+0]=f2tf(ra[i].x); sa[base+8]=f2tf(ra[i].y);
            sa[base+16]=f2tf(ra[i].z); sa[base+24]=f2tf(ra[i].w);
        }
        #pragma unroll
        for (int i = 0; i < 12; i++) {
            const int base = (lr + i * 32) * SROW + lc4;
            sb[base+0]=f2tf(rb[i].x); sb[base+8]=f2tf(rb[i].y);
            sb[base+16]=f2tf(rb[i].z); sb[base+24]=f2tf(rb[i].w);
        }
    }
    __syncthreads();

    for (int it = 0; it < nk; it++) {
        const bool more = (it + 1 < nk);
        if (more) {
            const int k = (it + 1) * 32 + lc4 * 4;
            #pragma unroll
            for (int i = 0; i < 2; i++)  ra[i] = *(const float4*)(aptr[i] + k);
            #pragma unroll
            for (int i = 0; i < 12; i++) rb[i] = *(const float4*)(wptr[i] + k);
        }
        const uint32_t* cur = sm + (it & 1) * R_STAGE;
        const uint4* As4 = (const uint4*)cur;
        const uint4* Bs4 = (const uint4*)(cur + R_A_U32);
        #pragma unroll
        for (int h = 0; h < 2; h++) {
            const int fo = q * 2 + h;
            const uint4 aL0 = As4[(wm0 + g     ) * 9 + fo];
            const uint4 aH0 = As4[(wm0 + g +  8) * 9 + fo];
            const uint4 aL1 = As4[(wm0 + g + 16) * 9 + fo];
            const uint4 aH1 = As4[(wm0 + g + 24) * 9 + fo];
            uint4 bf[3][4];
            #pragma unroll
            for (int gt = 0; gt < 3; gt++)
                #pragma unroll
                for (int nt = 0; nt < 4; nt++)
                    bf[gt][nt] = Bs4[(gt * 128 + wn0 + nt * 8 + g) * 9 + fo];
            #pragma unroll
            for (int s = 0; s < 2; s++) {
                const uint32_t A00 = s ? aL0.z : aL0.x;
                const uint32_t A20 = s ? aL0.w : aL0.y;
                const uint32_t A10 = s ? aH0.z : aH0.x;
                const uint32_t A30 = s ? aH0.w : aH0.y;
                const uint32_t A01 = s ? aL1.z : aL1.x;
                const uint32_t A21 = s ? aL1.w : aL1.y;
                const uint32_t A11 = s ? aH1.z : aH1.x;
                const uint32_t A31 = s ? aH1.w : aH1.y;
                #pragma unroll
                for (int gt = 0; gt < 3; gt++)
                    #pragma unroll
                    for (int nt = 0; nt < 4; nt++) {
                        const uint32_t B0 = s ? bf[gt][nt].z : bf[gt][nt].x;
                        const uint32_t B1 = s ? bf[gt][nt].w : bf[gt][nt].y;
                        mma8(c[gt][0][nt], A00, A10, A20, A30, B0, B1);
                        mma8(c[gt][1][nt], A01, A11, A21, A31, B0, B1);
                    }
            }
        }
        if (more) {
            uint32_t* nx = sm + ((it + 1) & 1) * R_STAGE;
            uint32_t* sa = nx;
            uint32_t* sb = nx + R_A_U32;
            #pragma unroll
            for (int i = 0; i < 2; i++) {
                const int base = (lr + i * 32) * SROW + lc4;
                sa[base+0]=f2tf(ra[i].x); sa[base+8]=f2tf(ra[i].y);
                sa[base+16]=f2tf(ra[i].z); sa[base+24]=f2tf(ra[i].w);
            }
            #pragma unroll
            for (int i = 0; i < 12; i++) {
                const int base = (lr + i * 32) * SROW + lc4;
                sb[base+0]=f2tf(rb[i].x); sb[base+8]=f2tf(rb[i].y);
                sb[base+16]=f2tf(rb[i].z); sb[base+24]=f2tf(rb[i].w);
            }
            __syncthreads();
        }
    }

    // ---- GRU cell epilogue ----
    #pragma unroll
    for (int mt = 0; mt < 2; mt++) {
        #pragma unroll
        for (int rr = 0; rr < 2; rr++) {           // row pair within fragment
            const int b = row0 + wm0 + mt * 16 + g + rr * 8;
            const int tok = inds[b * TT + tt];
            const float* gib = git + (long)tok * G3;
            #pragma unroll
            for (int nt = 0; nt < 4; nt++) {
                const int hcol = wn0 + nt * 8 + q * 2;   // within tile
                const int hg = col0 + hcol;              // global h index
                const int j0 = rr * 2;
                #pragma unroll
                for (int e = 0; e < 2; e++) {
                    const int hh = hg + e;
                    const float gir = gib[hh];
                    const float giz = gib[HID + hh];
                    const float gin = gib[2 * HID + hh];
                    const float ghr = c[0][mt][nt][j0 + e] + bhh[hh];
                    const float ghz = c[1][mt][nt][j0 + e] + bhh[HID + hh];
                    const float ghn = c[2][mt][nt][j0 + e] + bhh[2 * HID + hh];
                    const float hp = hprev[(long)b * HID + hh];
                    const float r = sigm(gir + ghr);
                    const float z = sigm(giz + ghz);
                    const float n = tanhf(gin + r * ghn);
                    const float hnew = (1.f - z) * n + z * hp;
                    hnext[(long)b * HID + hh] = hnew;
                    y_word[(long)(b * TT + tt) * DD + off + hh] = hnew;
                }
            }
        }
    }
}

// ---------------- fused attention logits (unchanged) ---------------------------
__global__ void __launch_bounds__(256) attn_w(
    const float* __restrict__ yw, const float* __restrict__ wl,
    const float* __restrict__ bl, const float* __restrict__ gw,
    const float* __restrict__ bc, float* __restrict__ wraw)
{
    extern __shared__ uint32_t sm[];
    __shared__ float red[128][9];

    const int tid  = threadIdx.x;
    const int lane = tid & 31, wid = tid >> 5;
    const int g = lane >> 2, q = lane & 3;
    const int wm0 = (wid & 3) * 32;
    const int wn0 = (wid >> 2) * 64;
    const int row0 = blockIdx.x * 128;
    const int lr  = tid >> 3;
    const int lc4 = tid & 7;

    const float* aptr[4];
    #pragma unroll
    for (int i = 0; i < 4; i++)
        aptr[i] = yw + (long)(row0 + lr + i * 32) * DD;

    int rb0[2], rb1[2];
    #pragma unroll
    for (int mt = 0; mt < 2; mt++) {
        const int r = row0 + wm0 + mt * 16 + g;
        rb0[mt] = r / TT;
        rb1[mt] = (r + 8) / TT;
    }
    float rowsum[2][2] = {{0.f, 0.f}, {0.f, 0.f}};

    float4 ra[4], rb[4];
    const int nk = DD / 32;

    for (int ct = 0; ct < DD / 128; ct++) {
        const int col0 = ct * 128;
        const float* wptr[4];
        #pragma unroll
        for (int i = 0; i < 4; i++)
            wptr[i] = wl + (long)(col0 + lr + i * 32) * DD;

        float c[2][8][4];
        #pragma unroll
        for (int mt = 0; mt < 2; mt++)
            #pragma unroll
            for (int nt = 0; nt < 8; nt++)
                #pragma unroll
                for (int j = 0; j < 4; j++) c[mt][nt][j] = 0.f;

        stage_load(aptr, wptr, lc4 * 4, DD, ra, rb);
        stage_store(sm, lr, lc4, ra, rb);
        __syncthreads();
        for (int it = 0; it < nk; it++) {
            const bool more = (it + 1 < nk);
            if (more) stage_load(aptr, wptr, (it + 1) * 32 + lc4 * 4, DD, ra, rb);
            const uint32_t* cur = sm + (it & 1) * (2 * STAGE_U32);
            mm_tile(cur, cur + STAGE_U32, wm0, wn0, g, q, c);
            if (more) {
                stage_store(sm + ((it + 1) & 1) * (2 * STAGE_U32), lr, lc4, ra, rb);
                __syncthreads();
            }
        }

        #pragma unroll
        for (int mt = 0; mt < 2; mt++) {
            #pragma unroll
            for (int nt = 0; nt < 8; nt++) {
                const int n = col0 + wn0 + nt * 8 + q * 2;
                const float bb0 = bl[n], bb1 = bl[n + 1];
                rowsum[mt][0] += tanhf(c[mt][nt][0] + bb0) * gw[(long)rb0[mt] * DD + n]
                               + tanhf(c[mt][nt][1] + bb1) * gw[(long)rb0[mt] * DD + n + 1];
                rowsum[mt][1] += tanhf(c[mt][nt][2] + bb0) * gw[(long)rb1[mt] * DD + n]
                               + tanhf(c[mt][nt][3] + bb1) * gw[(long)rb1[mt] * DD + n + 1];
            }
        }
        __syncthreads();
    }

    const int rc = (wid >> 2) * 4 + q;
    #pragma unroll
    for (int mt = 0; mt < 2; mt++) {
        red[wm0 + mt * 16 + g    ][rc] = rowsum[mt][0];
        red[wm0 + mt * 16 + g + 8][rc] = rowsum[mt][1];
    }
    __syncthreads();
    if (tid < 128) {
        float s = 0.f;
        #pragma unroll
        for (int x = 0; x < 8; x++) s += red[tid][x];
        wraw[row0 + tid] = s + bc[0];
    }
}

// ---------------- small kernels ------------------------------------------------
__global__ void zero_h(float* __restrict__ h_f, float* __restrict__ h_b)
{
    const int i = blockIdx.x * 256 + threadIdx.x;
    h_f[i] = 0.f;
    h_b[i] = 0.f;
}

__global__ void maxpool(const int* __restrict__ inds,
                        const float* __restrict__ y_word,
                        float* __restrict__ y_pool)
{
    const int idx = blockIdx.x * 256 + threadIdx.x;
    const int b = idx >> 10;
    const int d = idx & (DD - 1);
    float m = -INFINITY;
    #pragma unroll
    for (int t = 0; t < TT; t++) {
        if (inds[b * TT + t] != 0)
            m = fmaxf(m, y_word[(long)(b * TT + t) * DD + d]);
    }
    y_pool[idx] = m;
}

__global__ void softmax_out(const float* __restrict__ w_raw,
                            const float* __restrict__ y_word,
                            float* __restrict__ out)
{
    __shared__ float p[TT];
    const int b = blockIdx.x;
    if (threadIdx.x == 0) {
        float v[TT]; float mx = -INFINITY;
        #pragma unroll
        for (int t = 0; t < TT; t++) { v[t] = w_raw[b * TT + t]; mx = fmaxf(mx, v[t]); }
        float s = 0.f;
        #pragma unroll
        for (int t = 0; t < TT; t++) { v[t] = expf(v[t] - mx); s += v[t]; }
        const float inv = 1.f / s;
        #pragma unroll
        for (int t = 0; t < TT; t++) p[t] = v[t] * inv;
    }
    __syncthreads();
    for (int d = threadIdx.x; d < DD; d += 256) {
        float s = 0.f;
        #pragma unroll
        for (int t = 0; t < TT; t++)
            s += p[t] * y_word[((long)(b * TT + t)) * DD + d];
        out[(long)b * DD + d] = s;
    }
}

// ---------------- host launch --------------------------------------------------
extern "C" void kernel_launch(void* const* d_in, const int* in_sizes, int n_in,
                              void* d_out, int out_size)
{
    const int*   inds     = (const int*)  d_in[0];
    const float* emb      = (const float*)d_in[1];
    const float* w_ih_f   = (const float*)d_in[2];
    const float* w_hh_f   = (const float*)d_in[3];
    const float* b_ih_f   = (const float*)d_in[4];
    const float* b_hh_f   = (const float*)d_in[5];
    const float* w_ih_b   = (const float*)d_in[6];
    const float* w_hh_b   = (const float*)d_in[7];
    const float* b_ih_b   = (const float*)d_in[8];
    const float* b_hh_b   = (const float*)d_in[9];
    const float* w_local  = (const float*)d_in[10];
    const float* b_local  = (const float*)d_in[11];
    const float* w_global = (const float*)d_in[12];
    const float* b_global = (const float*)d_in[13];
    const float* w_common = (const float*)d_in[14];
    const float* b_common = (const float*)d_in[15];
    float* out = (float*)d_out;

    float *git_f, *git_b, *h_f, *h_b, *yw, *yp, *gw, *wraw;
    cudaGetSymbolAddress((void**)&git_f, g_git_f);
    cudaGetSymbolAddress((void**)&git_b, g_git_b);
    cudaGetSymbolAddress((void**)&h_f,  g_h_f);
    cudaGetSymbolAddress((void**)&h_b,  g_h_b);
    cudaGetSymbolAddress((void**)&yw,   g_yword);
    cudaGetSymbolAddress((void**)&yp,   g_ypool);
    cudaGetSymbolAddress((void**)&gw,   g_gw);
    cudaGetSymbolAddress((void**)&wraw, g_wraw);

    cudaFuncSetAttribute(tgemm,    cudaFuncAttributeMaxDynamicSharedMemorySize, SMEM_B);
    cudaFuncSetAttribute(attn_w,   cudaFuncAttributeMaxDynamicSharedMemorySize, SMEM_B);
    cudaFuncSetAttribute(rec_step, cudaFuncAttributeMaxDynamicSharedMemorySize, R_SMEM);

    // 1. zero hidden-state buffer 0
    zero_h<<<BH / 256, 256>>>(h_f, h_b);

    // 2. per-vocab gi table (incl. b_ih), both dirs
    dim3 gt_grid((VOCAB + 127) / 128, G3 / 128, 2);
    tgemm<<<gt_grid, 256, SMEM_B>>>(emb, emb, EMBD,
                                    w_ih_f, w_ih_b, b_ih_f, b_ih_b, nullptr,
                                    git_f, git_b, VOCAB, G3, EMBD, 0);

    // 3. fused bidirectional GRU recurrence (double-buffered h)
    dim3 rec_grid(BATCH / 64, HID / 128, 2);
    for (int t = 0; t < TT; t++) {
        const int cur = t & 1, nxt = (t + 1) & 1;
        rec_step<<<rec_grid, 256, R_SMEM>>>(inds, git_f, git_b,
                                            w_hh_f, w_hh_b, b_hh_f, b_hh_b,
                                            h_f + (size_t)cur * BH, h_b + (size_t)cur * BH,
                                            h_f + (size_t)nxt * BH, h_b + (size_t)nxt * BH,
                                            yw, t);
    }

    // 4. masked max pool
    maxpool<<<(BATCH * DD) / 256, 256>>>(inds, yw, yp);

    // 5. gw = tanh(y_pool @ w_global^T + b_global) * w_common
    dim3 gw_grid(BATCH / 128, DD / 128, 1);
    tgemm<<<gw_grid, 256, SMEM_B>>>(yp, yp, DD,
                                    w_global, w_global, b_global, b_global, w_common,
                                    gw, gw, BATCH, DD, DD, 1);

    // 6. fused l_emb -> tanh -> dot(gw) -> attention logits
    attn_w<<<BT / 128, 256, SMEM_B>>>(yw, w_local, b_local, gw, b_common, wraw);

    // 7. softmax over T + weighted sum
    softmax_out<<<BATCH, 256>>>(wraw, yw, out);
}